// round 6
// baseline (speedup 1.0000x reference)
#include <cuda_runtime.h>
#include <math.h>
#include <cstdint>

#define NB 4
#define NS 2048
#define ND 1024
#define NH 16
#define NKV 4
#define NHD 64
#define MTOT (NB * NS)   // 8192

// ---------------- scratch (static device globals; no allocation) -------------
__device__ float g_q[(size_t)MTOT * ND];
__device__ float g_k[(size_t)MTOT * NKV * NHD];
__device__ float g_v[(size_t)MTOT * NKV * NHD];
__device__ float g_o[(size_t)MTOT * ND];

// ---------------- helpers -----------------------------------------------------
__device__ __forceinline__ uint32_t f2tf(float f) {
    uint32_t r;
    asm("cvt.rna.tf32.f32 %0, %1;" : "=r"(r) : "f"(f));
    return r;
}
__device__ __forceinline__ float ex2(float x) {
    float y;
    asm("ex2.approx.f32 %0, %1;" : "=f"(y) : "f"(x));
    return y;
}
__device__ __forceinline__ uint32_t smem_u32(const void* p) {
    uint32_t a;
    asm("{ .reg .u64 t; cvta.to.shared.u64 t, %1; cvt.u32.u64 %0, t; }" : "=r"(a) : "l"(p));
    return a;
}
__device__ __forceinline__ void ldmx4(uint32_t* r, uint32_t addr) {
    asm volatile("ldmatrix.sync.aligned.m8n8.x4.shared.b16 {%0,%1,%2,%3}, [%4];"
                 : "=r"(r[0]), "=r"(r[1]), "=r"(r[2]), "=r"(r[3]) : "r"(addr));
}
__device__ __forceinline__ void ldmx2(uint32_t* r, uint32_t addr) {
    asm volatile("ldmatrix.sync.aligned.m8n8.x2.shared.b16 {%0,%1}, [%2];"
                 : "=r"(r[0]), "=r"(r[1]) : "r"(addr));
}
__device__ __forceinline__ void cpa16(uint32_t dst, const void* src) {
    asm volatile("cp.async.ca.shared.global [%0], [%1], 16;" :: "r"(dst), "l"(src));
}
__device__ __forceinline__ void cpa_commit() {
    asm volatile("cp.async.commit_group;" ::: "memory");
}
// D += A(16x8) * B(8x8), tf32, fp32 accum.
__device__ __forceinline__ void mma8(float* c, const uint32_t* a, const uint32_t* b) {
    asm volatile(
        "mma.sync.aligned.m16n8k8.row.col.f32.tf32.tf32.f32 "
        "{%0,%1,%2,%3}, {%4,%5,%6,%7}, {%8,%9}, {%0,%1,%2,%3};"
        : "+f"(c[0]), "+f"(c[1]), "+f"(c[2]), "+f"(c[3])
        : "r"(a[0]), "r"(a[1]), "r"(a[2]), "r"(a[3]), "r"(b[0]), "r"(b[1]));
}

// ---------------- tf32 GEMM (unchanged from R5) ------------------------------
#define AP 20
#define WPX 136

__device__ __forceinline__ void tgemm_body(const float* __restrict__ A,
                                           const float* __restrict__ W,
                                           float* __restrict__ C,
                                           int M, int N, int K,
                                           uint32_t (*As)[128 * AP],
                                           uint32_t (*Ws)[16 * WPX]) {
    const int tid = threadIdx.x, wid = tid >> 5, lane = tid & 31;
    const int g = lane >> 2, tg = lane & 3;
    const int bm = blockIdx.y, bn = blockIdx.x;
    const int wm = wid >> 1, wn = wid & 1;
    const int arow_l = (lane & 7) + ((lane >> 3) & 1) * 8;
    const int kcol_l = (lane >> 4) * 4;

    const uint32_t as_b = smem_u32(As);

    const int row_a = tid >> 2, ca = (tid & 3) * 4;
    const int kw = tid >> 5, nw = (tid & 31) * 4;
    const float* Ap = A + (size_t)(bm * 128 + row_a) * K + ca;
    const float* Wp = W + (size_t)kw * N + bn * 128 + nw;

    float acc[4][8][4];
#pragma unroll
    for (int i = 0; i < 4; i++)
#pragma unroll
        for (int j = 0; j < 8; j++)
#pragma unroll
            for (int r = 0; r < 4; r++) acc[i][j][r] = 0.f;

    const int nk = K / 16;

#pragma unroll
    for (int r = 0; r < 4; r++) {
        float4 av = *(const float4*)(Ap + (size_t)r * 32 * K);
        float4 wv = *(const float4*)(Wp + (size_t)r * 4 * N);
        *(uint4*)&As[0][(r * 32 + row_a) * AP + ca] =
            make_uint4(f2tf(av.x), f2tf(av.y), f2tf(av.z), f2tf(av.w));
        *(uint4*)&Ws[0][(r * 4 + kw) * WPX + nw] =
            make_uint4(f2tf(wv.x), f2tf(wv.y), f2tf(wv.z), f2tf(wv.w));
    }
    __syncthreads();

    for (int kt = 0; kt < nk; kt++) {
        const int buf = kt & 1;
        const bool more = (kt + 1) < nk;
        float4 av[4], wv[4];
        if (more) {
#pragma unroll
            for (int r = 0; r < 4; r++) {
                av[r] = *(const float4*)(Ap + (kt + 1) * 16 + (size_t)r * 32 * K);
                wv[r] = *(const float4*)(Wp + (size_t)((kt + 1) * 16 + r * 4) * N);
            }
        }

#pragma unroll
        for (int ks = 0; ks < 2; ks++) {
            const int k0 = ks * 8;
            uint32_t a[4][4];
#pragma unroll
            for (int mt = 0; mt < 4; mt++)
                ldmx4(a[mt], as_b + (uint32_t)(buf * 128 * AP +
                        (wm * 64 + mt * 16 + arow_l) * AP + k0 + kcol_l) * 4);
#pragma unroll
            for (int nt = 0; nt < 8; nt++) {
                uint32_t b[2];
                int cn = wn * 64 + nt * 8 + g;
                b[0] = Ws[buf][(k0 + tg) * WPX + cn];
                b[1] = Ws[buf][(k0 + tg + 4) * WPX + cn];
                mma8(acc[0][nt], a[0], b);
                mma8(acc[1][nt], a[1], b);
                mma8(acc[2][nt], a[2], b);
                mma8(acc[3][nt], a[3], b);
            }
        }

        if (more) {
            const int nb = buf ^ 1;
#pragma unroll
            for (int r = 0; r < 4; r++) {
                *(uint4*)&As[nb][(r * 32 + row_a) * AP + ca] =
                    make_uint4(f2tf(av[r].x), f2tf(av[r].y), f2tf(av[r].z), f2tf(av[r].w));
                *(uint4*)&Ws[nb][(r * 4 + kw) * WPX + nw] =
                    make_uint4(f2tf(wv[r].x), f2tf(wv[r].y), f2tf(wv[r].z), f2tf(wv[r].w));
            }
        }
        __syncthreads();
    }

#pragma unroll
    for (int mt = 0; mt < 4; mt++)
#pragma unroll
        for (int nt = 0; nt < 8; nt++) {
            int row = bm * 128 + wm * 64 + mt * 16 + g;
            int col = bn * 128 + wn * 64 + nt * 8 + 2 * tg;
            *(float2*)(C + (size_t)row * N + col) = make_float2(acc[mt][nt][0], acc[mt][nt][1]);
            *(float2*)(C + (size_t)(row + 8) * N + col) = make_float2(acc[mt][nt][2], acc[mt][nt][3]);
        }
}

__global__ __launch_bounds__(128) void tgemm(const float* __restrict__ A,
                                             const float* __restrict__ W,
                                             float* __restrict__ C,
                                             int M, int N, int K) {
    __shared__ uint32_t As[2][128 * AP];
    __shared__ uint32_t Ws[2][16 * WPX];
    tgemm_body(A, W, C, M, N, K, As, Ws);
}

__global__ __launch_bounds__(128) void tgemm_dual(const float* __restrict__ A,
                                                  const float* __restrict__ W0,
                                                  const float* __restrict__ W1,
                                                  float* __restrict__ C0,
                                                  float* __restrict__ C1,
                                                  int M, int N, int K) {
    __shared__ uint32_t As[2][128 * AP];
    __shared__ uint32_t Ws[2][16 * WPX];
    const float* W = blockIdx.z ? W1 : W0;
    float* C = blockIdx.z ? C1 : C0;
    tgemm_body(A, W, C, M, N, K, As, Ws);
}

// ---------------- Flash attention: cp.async K pipeline, hidden V loads -------
// Block 128 thr (4 warps); q-tile 128 (32 rows/warp); kv chunks of 64.
// smem: P/Q overlay [128][QP], K double buf [2][64][QP] (raw f32 -> tf32 in
// place), V single buf [64][VP] (tf32, written from regs mid-chunk).
#define QP 68
#define VP 72
#define SM_P 0
#define SM_K (128 * QP)                 // 8704
#define SM_V (SM_K + 2 * 64 * QP)       // 8704 + 8704
#define SM_TOT (SM_V + 64 * VP)         // 22016 words = 88064 B

__global__ void __launch_bounds__(128, 2) attn_mma() {
    extern __shared__ uint32_t sm4[];
    const uint32_t smb = smem_u32(sm4);
    uint32_t* Ps = sm4 + SM_P;
    uint32_t* Vs = sm4 + SM_V;

    const int qb = blockIdx.x, h = blockIdx.y, b = blockIdx.z;
    const int kvh = h >> 2;
    const int tid = threadIdx.x, w = tid >> 5, lane = tid & 31;
    const int g = lane >> 2, tg = lane & 3;
    const int arow_l = (lane & 7) + ((lane >> 3) & 1) * 8;
    const int kcol_l = (lane >> 4) * 4;
    const int brow_l = lane & 7, bk_l = ((lane >> 3) & 1) * 4;

    const float LOG2E = 1.4426950408889634f;
    const float sc2 = 0.125f * LOG2E;
    const float slope2 = ex2(-0.5f * (float)(h + 1)) * LOG2E;

    // per-thread loader coords (8 reps x 128 thr cover 64 rows x 16 col4)
    const int lr = tid >> 4;            // row within 8-row rep group
    const int lc = (tid & 15) * 4;      // col (floats)

    const float* kbase = g_k + (size_t)(b * NS) * (NKV * NHD) + kvh * NHD;
    const float* vbase = g_v + (size_t)(b * NS) * (NKV * NHD) + kvh * NHD;

    // prologue: start K chunk 0 loads immediately
#pragma unroll
    for (int rep = 0; rep < 8; rep++) {
        int r = rep * 8 + lr;
        cpa16(smb + (uint32_t)(SM_K + r * QP + lc) * 4, kbase + (size_t)r * 256 + lc);
    }
    cpa_commit();

    // stage Q tile [128 x 64] (tf32) into P region
    {
        const float* qbase = g_q + (size_t)(b * NS + qb * 128) * ND + h * NHD;
#pragma unroll
        for (int rep = 0; rep < 16; rep++) {
            int r = rep * 8 + lr;
            float4 v = *(const float4*)(qbase + (size_t)r * ND + lc);
            *(uint4*)&Ps[r * QP + lc] = make_uint4(f2tf(v.x), f2tf(v.y), f2tf(v.z), f2tf(v.w));
        }
    }
    __syncthreads();

    // Q fragments -> registers
    uint32_t qf[8][2][4];
#pragma unroll
    for (int ks = 0; ks < 8; ks++)
#pragma unroll
        for (int mt = 0; mt < 2; mt++)
            ldmx4(qf[ks][mt], smb + (uint32_t)(SM_P +
                    (w * 32 + mt * 16 + arow_l) * QP + ks * 8 + kcol_l) * 4);

    float m[4], l[4], O[2][8][4];
#pragma unroll
    for (int i = 0; i < 4; i++) { m[i] = -INFINITY; l[i] = 0.f; }
#pragma unroll
    for (int mt = 0; mt < 2; mt++)
#pragma unroll
        for (int nt = 0; nt < 8; nt++)
#pragma unroll
            for (int r = 0; r < 4; r++) O[mt][nt][r] = 0.f;

    float rowi[4];
#pragma unroll
    for (int mt = 0; mt < 2; mt++) {
        rowi[2 * mt]     = (float)(qb * 128 + w * 32 + mt * 16 + g);
        rowi[2 * mt + 1] = rowi[2 * mt] + 8.f;
    }

    const int NCH = NS / 64;
    for (int kt = 0; kt < NCH; kt++) {
        const int kb = kt & 1;
        const bool more = (kt + 1) < NCH;
        if (more) {
            const float* kn = kbase + (size_t)(kt + 1) * 64 * 256;
            const uint32_t kdst = SM_K + (kb ^ 1) * 64 * QP;
#pragma unroll
            for (int rep = 0; rep < 8; rep++) {
                int r = rep * 8 + lr;
                cpa16(smb + (uint32_t)(kdst + r * QP + lc) * 4, kn + (size_t)r * 256 + lc);
            }
            cpa_commit();
            asm volatile("cp.async.wait_group 1;" ::: "memory");
        } else {
            asm volatile("cp.async.wait_group 0;" ::: "memory");
        }
        __syncthreads();  // (A) K(kt) raw visible; prev chunk compute done

        // V half0 LDG (rows 0..31) -- latency hidden by K-convert + S mt0
        const float* vp = vbase + (size_t)kt * 64 * 256;
        float4 vr[4];
#pragma unroll
        for (int rep = 0; rep < 4; rep++)
            vr[rep] = *(const float4*)(vp + (size_t)(rep * 8 + lr) * 256 + lc);

        // K convert in place: raw f32 -> tf32
        const uint32_t kcur = SM_K + kb * 64 * QP;
#pragma unroll
        for (int rep = 0; rep < 8; rep++) {
            int r = rep * 8 + lr;
            uint4 raw = *(uint4*)&sm4[kcur + r * QP + lc];
            *(uint4*)&sm4[kcur + r * QP + lc] = make_uint4(
                f2tf(__uint_as_float(raw.x)), f2tf(__uint_as_float(raw.y)),
                f2tf(__uint_as_float(raw.z)), f2tf(__uint_as_float(raw.w)));
        }
        __syncthreads();  // (B) K tf32 ready

        // ---- per-mt: S = Q K^T, softmax, P write; V staged between ----
#pragma unroll
        for (int mt = 0; mt < 2; mt++) {
            float S[8][4];
#pragma unroll
            for (int nt = 0; nt < 8; nt++)
#pragma unroll
                for (int r = 0; r < 4; r++) S[nt][r] = 0.f;

#pragma unroll
            for (int ks = 0; ks < 8; ks++) {
#pragma unroll
                for (int nt = 0; nt < 8; nt++) {
                    uint32_t bb[2];
                    ldmx2(bb, smb + (uint32_t)(kcur +
                            (nt * 8 + brow_l) * QP + ks * 8 + bk_l) * 4);
                    mma8(S[nt], qf[ks][mt], bb);
                }
            }

            float mx0 = -INFINITY, mx1 = -INFINITY;
#pragma unroll
            for (int nt = 0; nt < 8; nt++) {
                float j0 = (float)(kt * 64 + nt * 8 + 2 * tg);
                S[nt][0] = S[nt][0] * sc2 + slope2 * (j0 - rowi[2 * mt]);
                S[nt][1] = S[nt][1] * sc2 + slope2 * (j0 + 1.f - rowi[2 * mt]);
                S[nt][2] = S[nt][2] * sc2 + slope2 * (j0 - rowi[2 * mt + 1]);
                S[nt][3] = S[nt][3] * sc2 + slope2 * (j0 + 1.f - rowi[2 * mt + 1]);
                mx0 = fmaxf(mx0, fmaxf(S[nt][0], S[nt][1]));
                mx1 = fmaxf(mx1, fmaxf(S[nt][2], S[nt][3]));
            }
            mx0 = fmaxf(mx0, __shfl_xor_sync(0xffffffffu, mx0, 1));
            mx0 = fmaxf(mx0, __shfl_xor_sync(0xffffffffu, mx0, 2));
            mx1 = fmaxf(mx1, __shfl_xor_sync(0xffffffffu, mx1, 1));
            mx1 = fmaxf(mx1, __shfl_xor_sync(0xffffffffu, mx1, 2));

            float mn0 = fmaxf(m[2 * mt], mx0), mn1 = fmaxf(m[2 * mt + 1], mx1);
            float f0 = ex2(m[2 * mt] - mn0), f1 = ex2(m[2 * mt + 1] - mn1);
            m[2 * mt] = mn0; m[2 * mt + 1] = mn1;

            float rs0 = 0.f, rs1 = 0.f;
#pragma unroll
            for (int nt = 0; nt < 8; nt++) {
                S[nt][0] = ex2(S[nt][0] - mn0);
                S[nt][1] = ex2(S[nt][1] - mn0);
                S[nt][2] = ex2(S[nt][2] - mn1);
                S[nt][3] = ex2(S[nt][3] - mn1);
                rs0 += S[nt][0] + S[nt][1];
                rs1 += S[nt][2] + S[nt][3];
            }
            rs0 += __shfl_xor_sync(0xffffffffu, rs0, 1);
            rs0 += __shfl_xor_sync(0xffffffffu, rs0, 2);
            rs1 += __shfl_xor_sync(0xffffffffu, rs1, 1);
            rs1 += __shfl_xor_sync(0xffffffffu, rs1, 2);
            l[2 * mt] = l[2 * mt] * f0 + rs0;
            l[2 * mt + 1] = l[2 * mt + 1] * f1 + rs1;

#pragma unroll
            for (int nt = 0; nt < 8; nt++) {
                O[mt][nt][0] *= f0; O[mt][nt][1] *= f0;
                O[mt][nt][2] *= f1; O[mt][nt][3] *= f1;
            }

            int rL = w * 32 + mt * 16 + g, rH = rL + 8;
#pragma unroll
            for (int nt = 0; nt < 8; nt++) {
                *(uint2*)&Ps[rL * QP + nt * 8 + 2 * tg] =
                    make_uint2(f2tf(S[nt][0]), f2tf(S[nt][1]));
                *(uint2*)&Ps[rH * QP + nt * 8 + 2 * tg] =
                    make_uint2(f2tf(S[nt][2]), f2tf(S[nt][3]));
            }

            // stage V half into smem (tf32); kick off half1 LDG after half0
            if (mt == 0) {
#pragma unroll
                for (int rep = 0; rep < 4; rep++)
                    *(uint4*)&Vs[(rep * 8 + lr) * VP + lc] = make_uint4(
                        f2tf(vr[rep].x), f2tf(vr[rep].y), f2tf(vr[rep].z), f2tf(vr[rep].w));
#pragma unroll
                for (int rep = 0; rep < 4; rep++)
                    vr[rep] = *(const float4*)(vp + (size_t)(32 + rep * 8 + lr) * 256 + lc);
            } else {
#pragma unroll
                for (int rep = 0; rep < 4; rep++)
                    *(uint4*)&Vs[(32 + rep * 8 + lr) * VP + lc] = make_uint4(
                        f2tf(vr[rep].x), f2tf(vr[rep].y), f2tf(vr[rep].z), f2tf(vr[rep].w));
            }
        }
        __syncthreads();  // (C) V complete + P written

        // O += P @ V
#pragma unroll
        for (int ks = 0; ks < 8; ks++) {
            const int k0 = ks * 8;
            uint32_t a[2][4];
#pragma unroll
            for (int mt = 0; mt < 2; mt++)
                ldmx4(a[mt], smb + (uint32_t)(SM_P +
                        (w * 32 + mt * 16 + arow_l) * QP + k0 + kcol_l) * 4);
#pragma unroll
            for (int nt = 0; nt < 8; nt++) {
                uint32_t bb[2];
                bb[0] = Vs[(k0 + tg) * VP + nt * 8 + g];
                bb[1] = Vs[(k0 + tg + 4) * VP + nt * 8 + g];
                mma8(O[0][nt], a[0], bb);
                mma8(O[1][nt], a[1], bb);
            }
        }
    }

    // epilogue
#pragma unroll
    for (int mt = 0; mt < 2; mt++) {
        float inv0 = 1.f / l[2 * mt], inv1 = 1.f / l[2 * mt + 1];
        int rL = qb * 128 + w * 32 + mt * 16 + g;
        float* ob = g_o + (size_t)(b * NS + rL) * ND + h * NHD;
#pragma unroll
        for (int nt = 0; nt < 8; nt++) {
            *(float2*)(ob + nt * 8 + 2 * tg) =
                make_float2(O[mt][nt][0] * inv0, O[mt][nt][1] * inv0);
            *(float2*)(ob + (size_t)8 * ND + nt * 8 + 2 * tg) =
                make_float2(O[mt][nt][2] * inv1, O[mt][nt][3] * inv1);
        }
    }
}

// ---------------- launch ------------------------------------------------------
extern "C" void kernel_launch(void* const* d_in, const int* in_sizes, int n_in,
                              void* d_out, int out_size) {
    const float* x  = (const float*)d_in[0];
    const float* Wq = (const float*)d_in[1];
    const float* Wk = (const float*)d_in[2];
    const float* Wv = (const float*)d_in[3];
    const float* Wo = (const float*)d_in[4];
    float* out = (float*)d_out;

    float *q, *k, *v, *o;
    cudaGetSymbolAddress((void**)&q, g_q);
    cudaGetSymbolAddress((void**)&k, g_k);
    cudaGetSymbolAddress((void**)&v, g_v);
    cudaGetSymbolAddress((void**)&o, g_o);

    const int smem_attn = SM_TOT * sizeof(uint32_t);   // 88064 B
    cudaFuncSetAttribute(attn_mma, cudaFuncAttributeMaxDynamicSharedMemorySize, smem_attn);

    tgemm<<<dim3(ND / 128, MTOT / 128), 128>>>(x, Wq, q, MTOT, ND, ND);
    tgemm_dual<<<dim3(256 / 128, MTOT / 128, 2), 128>>>(x, Wk, Wv, k, v, MTOT, 256, ND);

    attn_mma<<<dim3(NS / 128, NH, NB), 128, smem_attn>>>();

    tgemm<<<dim3(ND / 128, MTOT / 128), 128>>>(o, Wo, out, MTOT, ND, ND);
}